// round 7
// baseline (speedup 1.0000x reference)
#include <cuda_runtime.h>
#include <cuda_fp16.h>
#include <cstdint>

// Scratch (allocation-free rule: device globals)
__device__ __align__(16) __half g_qh[4194304];
__device__ __align__(16) __half g_kh[4194304];
__device__ __align__(16) __half g_vh[4194304];
__device__ __align__(16) __half g_xh[4194304];   // attention out (half), [B*N, D]
__device__ __align__(16) __half g_hh[4194304];   // MLP hidden (half), [B*N, D]
__device__ __align__(16) __half g_w1h[1048576];  // W1^T [out][in] half
__device__ __align__(16) __half g_w2h[1048576];  // W2^T [out][in] half

__device__ __forceinline__ uint32_t h2u(float a, float b) {
    __half2 h = __floats2half2_rn(a, b);
    return *reinterpret_cast<uint32_t*>(&h);
}
__device__ __forceinline__ uint32_t smem_u32(const void* p) {
    uint32_t a;
    asm("{ .reg .u64 t; cvta.to.shared.u64 t, %1; cvt.u32.u64 %0, t; }" : "=r"(a) : "l"(p));
    return a;
}
__device__ __forceinline__ void cpa16(uint32_t dst, const void* src) {
    asm volatile("cp.async.cg.shared.global [%0], [%1], 16;" :: "r"(dst), "l"(src));
}
#define CP_COMMIT() asm volatile("cp.async.commit_group;" ::: "memory")
#define CP_WAIT(n)  asm volatile("cp.async.wait_group %0;" :: "n"(n) : "memory")

__device__ __forceinline__ void ldsm4(uint32_t* r, uint32_t a) {
    asm volatile("ldmatrix.sync.aligned.m8n8.x4.shared.b16 {%0,%1,%2,%3}, [%4];"
        : "=r"(r[0]), "=r"(r[1]), "=r"(r[2]), "=r"(r[3]) : "r"(a));
}
__device__ __forceinline__ void ldsm4t(uint32_t* r, uint32_t a) {
    asm volatile("ldmatrix.sync.aligned.m8n8.x4.trans.shared.b16 {%0,%1,%2,%3}, [%4];"
        : "=r"(r[0]), "=r"(r[1]), "=r"(r[2]), "=r"(r[3]) : "r"(a));
}

// fp32-accumulate MMA
__device__ __forceinline__ void mma16(float* c, const uint32_t* a, const uint32_t* b) {
    asm volatile("mma.sync.aligned.m16n8k16.row.col.f32.f16.f16.f32 "
        "{%0,%1,%2,%3}, {%4,%5,%6,%7}, {%8,%9}, {%0,%1,%2,%3};"
        : "+f"(c[0]), "+f"(c[1]), "+f"(c[2]), "+f"(c[3])
        : "r"(a[0]), "r"(a[1]), "r"(a[2]), "r"(a[3]), "r"(b[0]), "r"(b[1]));
}
// fp16-accumulate MMA (C/D = 2 regs of half2)
__device__ __forceinline__ void mma16h(uint32_t* c, const uint32_t* a, const uint32_t* b) {
    asm volatile("mma.sync.aligned.m16n8k16.row.col.f16.f16.f16.f16 "
        "{%0,%1}, {%2,%3,%4,%5}, {%6,%7}, {%0,%1};"
        : "+r"(c[0]), "+r"(c[1])
        : "r"(a[0]), "r"(a[1]), "r"(a[2]), "r"(a[3]), "r"(b[0]), "r"(b[1]));
}
__device__ __forceinline__ uint32_t ex2h2(uint32_t x) {
    uint32_t r; asm("ex2.approx.f16x2 %0, %1;" : "=r"(r) : "r"(x)); return r;
}
__device__ __forceinline__ uint32_t mulh2(uint32_t a, uint32_t b) {
    uint32_t r; asm("mul.rn.f16x2 %0, %1, %2;" : "=r"(r) : "r"(a), "r"(b)); return r;
}

// ---------------------------------------------------------------------------
// Prep: q/k/v fp32 -> fp16 (one launch), W transpose+cvt
// ---------------------------------------------------------------------------
__global__ void cvt3(const float4* __restrict__ q, const float4* __restrict__ k,
                     const float4* __restrict__ v, uint2* __restrict__ qo,
                     uint2* __restrict__ ko, uint2* __restrict__ vo)
{
    int i = blockIdx.x * blockDim.x + threadIdx.x;
    const float4* s = blockIdx.y == 0 ? q : (blockIdx.y == 1 ? k : v);
    uint2* d = blockIdx.y == 0 ? qo : (blockIdx.y == 1 ? ko : vo);
    float4 t = s[i];
    uint2 o; o.x = h2u(t.x, t.y); o.y = h2u(t.z, t.w);
    d[i] = o;
}

__global__ void transpose_h(const float* __restrict__ src, __half* __restrict__ dst)
{
    __shared__ float t[32][33];
    int x = blockIdx.x * 32 + threadIdx.x;
    int y = blockIdx.y * 32 + threadIdx.y;
    #pragma unroll
    for (int j = 0; j < 32; j += 8)
        t[threadIdx.y + j][threadIdx.x] = src[(size_t)(y + j) * 1024 + x];
    __syncthreads();
    x = blockIdx.y * 32 + threadIdx.x;
    y = blockIdx.x * 32 + threadIdx.y;
    #pragma unroll
    for (int j = 0; j < 32; j += 8)
        dst[(size_t)(y + j) * 1024 + x] = __float2half_rn(t[threadIdx.x][threadIdx.y + j]);
}

// ---------------------------------------------------------------------------
// Attention softmax part only: xout = softmax(Q K^T * scale) @ V   (half)
// fp16-accumulate MMAs; softmax = HMUL2+EX2 on the S D-fragments in place;
// P fragments feed P@V with zero rearrangement. Row sums via P @ ones MMA.
// pe @ V is added by pev_kernel afterwards.
// ---------------------------------------------------------------------------
#define TB 9216                 // 64 rows * 144B
#define RSB 144

__global__ __launch_bounds__(128, 4)
void attn_kernel(const __half* __restrict__ qh, const __half* __restrict__ kh,
                 const __half* __restrict__ vh, __half* __restrict__ xout)
{
    extern __shared__ __align__(16) char smem[];
    const uint32_t sb = smem_u32(smem);

    const int b = blockIdx.x, h = blockIdx.y, q0 = blockIdx.z * 64;
    const int tid = threadIdx.x, lane = tid & 31, warp = tid >> 5;
    const int quad = lane >> 2, qt = lane & 3;
    const int rl0 = warp * 16 + quad, rh0 = rl0 + 8;

    const __half* qb = qh + ((size_t)(b * 16 + h) * 1024 + q0) * 64;
    const __half* kb = kh + (size_t)(b * 16 + h) * 65536;
    const __half* vb = vh + (size_t)(b * 16 + h) * 65536;

    int crow[4], ccol[4];
    #pragma unroll
    for (int i = 0; i < 4; ++i) {
        int c = tid + i * 128;
        crow[i] = c >> 3;
        ccol[i] = (c & 7) * 8;
    }

    auto issue_tile = [&](int kt, int buf) {
        const int k0 = kt * 64;
        const uint32_t Kb = sb + TB * (1 + buf * 2);
        const uint32_t Vb = Kb + TB;
        #pragma unroll
        for (int i = 0; i < 4; ++i) {
            uint32_t d = crow[i] * RSB + ccol[i] * 2;
            cpa16(Kb + d, kb + (size_t)(k0 + crow[i]) * 64 + ccol[i]);
            cpa16(Vb + d, vb + (size_t)(k0 + crow[i]) * 64 + ccol[i]);
        }
    };

    #pragma unroll
    for (int i = 0; i < 4; ++i)
        cpa16(sb + crow[i] * RSB + ccol[i] * 2, qb + (size_t)crow[i] * 64 + ccol[i]);
    issue_tile(0, 0);
    CP_COMMIT();

    const uint32_t laneA = (lane & 15) * RSB + (lane >> 4) * 16;
    const uint32_t laneK = ((lane & 7) + (lane >> 4) * 8) * RSB + ((lane >> 3) & 1) * 16;
    const uint32_t laneV = ((lane & 7) + ((lane >> 3) & 1) * 8) * RSB + (lane >> 4) * 16;

    uint32_t qa[4][4];
    uint32_t os2[8][2] = {};       // P@V, fp16 accum
    uint32_t rsum[2] = {};         // P@1, fp16 accum
    const float c2f = 0.125f * 1.44269504088896340736f;
    const uint32_t c2h = h2u(c2f, c2f);
    const uint32_t ones[2] = {0x3C003C00u, 0x3C003C00u};

    for (int kt = 0; kt < 16; ++kt) {
        const int buf = kt & 1;
        if (kt < 15) { issue_tile(kt + 1, buf ^ 1); CP_COMMIT(); CP_WAIT(1); }
        else CP_WAIT(0);
        __syncthreads();

        if (kt == 0) {
            #pragma unroll
            for (int kg = 0; kg < 4; ++kg)
                ldsm4(qa[kg], sb + warp * 16 * RSB + kg * 32 + laneA);
        }

        const uint32_t Kb = sb + TB * (1 + buf * 2);
        const uint32_t Vb = Kb + TB;

        // ----- S = Q @ K^T (fp16 accum) -----
        uint32_t pd[8][2] = {};
        #pragma unroll
        for (int kg = 0; kg < 4; ++kg)
            #pragma unroll
            for (int ngp = 0; ngp < 4; ++ngp) {
                uint32_t kf[4];
                ldsm4(kf, Kb + ngp * (16 * RSB) + kg * 32 + laneK);
                mma16h(pd[2 * ngp], qa[kg], kf);
                mma16h(pd[2 * ngp + 1], qa[kg], kf + 2);
            }

        // ----- P = exp2(S * c2), in place on fragments -----
        #pragma unroll
        for (int ng = 0; ng < 8; ++ng) {
            pd[ng][0] = ex2h2(mulh2(pd[ng][0], c2h));
            pd[ng][1] = ex2h2(mulh2(pd[ng][1], c2h));
        }

        // ----- os += P @ V ; rsum += P @ 1 -----
        #pragma unroll
        for (int kg = 0; kg < 4; ++kg) {
            uint32_t pa[4] = {pd[2 * kg][0], pd[2 * kg][1],
                              pd[2 * kg + 1][0], pd[2 * kg + 1][1]};
            mma16h(rsum, pa, ones);
            #pragma unroll
            for (int ngp = 0; ngp < 4; ++ngp) {
                uint32_t vf[4];
                ldsm4t(vf, Vb + kg * (16 * RSB) + ngp * 32 + laneV);
                mma16h(os2[2 * ngp],     pa, vf);
                mma16h(os2[2 * ngp + 1], pa, vf + 2);
            }
        }
        __syncthreads();
    }

    // Epilogue: xout = os / rowsum (half), layout [b, n, h*64 + c]
    const float il = 1.f / __low2float(*reinterpret_cast<__half2*>(&rsum[0]));
    const float ih = 1.f / __low2float(*reinterpret_cast<__half2*>(&rsum[1]));
    #pragma unroll
    for (int ng = 0; ng < 8; ++ng) {
        const int col = h * 64 + ng * 8 + qt * 2;
        float2 lo = __half22float2(*reinterpret_cast<__half2*>(&os2[ng][0]));
        float2 hi = __half22float2(*reinterpret_cast<__half2*>(&os2[ng][1]));
        *(uint32_t*)(xout + ((size_t)b * 1024 + q0 + rl0) * 1024 + col) =
            h2u(lo.x * il, lo.y * il);
        *(uint32_t*)(xout + ((size_t)b * 1024 + q0 + rh0) * 1024 + col) =
            h2u(hi.x * ih, hi.y * ih);
    }
}

// ---------------------------------------------------------------------------
// pe @ V batched GEMM (fp32 accum), accumulating into xout.
// Per h: C[1024, 256] = pe[h] (1024 x 1024, fp32, converted inline) @ Vcat,
// Vcat cols = (b*64 + c). CTA tile M=64, N=256; 256 threads (2 M x 4 N warps).
// Epilogue: xout[b][n][h*64+c] += C  (read-modify-write half).
// ---------------------------------------------------------------------------
#define EVA_TB 9216             // A buf: 64 rows * 144B
#define EVV_RS 528              // V row stride: 256 halves + pad
#define EVV_TB (64 * 528)       // 33792

__global__ __launch_bounds__(256, 2)
void pev_kernel(const float* __restrict__ pe, const __half* __restrict__ vh,
                __half* __restrict__ xout)
{
    extern __shared__ __align__(16) char smem[];
    const uint32_t sb = smem_u32(smem);

    const int m0 = blockIdx.x * 64, h = blockIdx.y;
    const int tid = threadIdx.x, lane = tid & 31, warp = tid >> 5;
    const int wr = warp & 1, wc = warp >> 1;
    const int quad = lane >> 2, qt = lane & 3;

    // A (pe) LDG decomposition: 4 float4 per thread per chunk
    int arow[4], acol[4];
    #pragma unroll
    for (int i = 0; i < 4; ++i) {
        int t = tid + i * 256;
        arow[i] = t >> 4;
        acol[i] = (t & 15) * 4;
    }
    // V cp.async decomposition: 8 chunks of 16B per thread
    int vrow[8], vseg[8];
    #pragma unroll
    for (int i = 0; i < 8; ++i) {
        int t = tid + i * 256;
        vrow[i] = t >> 5;
        vseg[i] = t & 31;
    }

    const float* peb = pe + (size_t)h * 1048576;

    uint32_t stage[8];
    auto ldg_cvt = [&](int kc) {
        #pragma unroll
        for (int i = 0; i < 4; ++i) {
            float4 t = *(const float4*)(peb + (size_t)(m0 + arow[i]) * 1024 + kc * 64 + acol[i]);
            stage[2 * i]     = h2u(t.x, t.y);
            stage[2 * i + 1] = h2u(t.z, t.w);
        }
    };
    auto sts_stage = [&](int buf) {
        uint32_t Ab = sb + buf * EVA_TB;
        #pragma unroll
        for (int i = 0; i < 4; ++i)
            *(uint2*)(smem + (Ab - sb) + arow[i] * RSB + acol[i] * 2) =
                make_uint2(stage[2 * i], stage[2 * i + 1]);
    };
    auto issue_v = [&](int kc, int buf) {
        uint32_t Vb = sb + 2 * EVA_TB + buf * EVV_TB;
        #pragma unroll
        for (int i = 0; i < 8; ++i) {
            int bb = vseg[i] >> 3, c8 = (vseg[i] & 7) * 8;
            cpa16(Vb + vrow[i] * EVV_RS + vseg[i] * 16,
                  vh + ((size_t)(bb * 16 + h) * 1024 + kc * 64 + vrow[i]) * 64 + c8);
        }
    };

    const uint32_t laneA = (lane & 15) * RSB + (lane >> 4) * 16;
    const uint32_t laneV = ((lane & 7) + ((lane >> 3) & 1) * 8) * EVV_RS + (lane >> 4) * 16;

    float acc[2][8][4] = {};

    ldg_cvt(0);
    issue_v(0, 0);
    CP_COMMIT();

    for (int kc = 0; kc < 16; ++kc) {
        const int buf = kc & 1;
        sts_stage(buf);
        if (kc < 15) {
            ldg_cvt(kc + 1);
            issue_v(kc + 1, buf ^ 1);
            CP_COMMIT();
            CP_WAIT(1);
        } else CP_WAIT(0);
        __syncthreads();

        const uint32_t Ab = sb + buf * EVA_TB;
        const uint32_t Vb = sb + 2 * EVA_TB + buf * EVV_TB;

        #pragma unroll
        for (int kg = 0; kg < 4; ++kg) {
            uint32_t a0[4], a1[4];
            ldsm4(a0, Ab + (wr * 32) * RSB + kg * 32 + laneA);
            ldsm4(a1, Ab + (wr * 32 + 16) * RSB + kg * 32 + laneA);
            #pragma unroll
            for (int nb = 0; nb < 4; ++nb) {
                uint32_t vf[4];
                ldsm4t(vf, Vb + (kg * 16) * EVV_RS + wc * 128 + nb * 32 + laneV);
                mma16(acc[0][2 * nb],     a0, vf);
                mma16(acc[0][2 * nb + 1], a0, vf + 2);
                mma16(acc[1][2 * nb],     a1, vf);
                mma16(acc[1][2 * nb + 1], a1, vf + 2);
            }
        }
        __syncthreads();
    }

    // Epilogue: xout[wc][row][h*64 + col] += acc  (wc == batch b)
    #pragma unroll
    for (int s = 0; s < 2; ++s) {
        const int row = m0 + wr * 32 + s * 16 + quad;
        #pragma unroll
        for (int ng = 0; ng < 8; ++ng) {
            const int col = h * 64 + ng * 8 + qt * 2;
            uint32_t* p0 = (uint32_t*)(xout + ((size_t)wc * 1024 + row) * 1024 + col);
            uint32_t* p1 = (uint32_t*)(xout + ((size_t)wc * 1024 + row + 8) * 1024 + col);
            float2 e0 = __half22float2(*reinterpret_cast<__half2*>(p0));
            float2 e1 = __half22float2(*reinterpret_cast<__half2*>(p1));
            *p0 = h2u(e0.x + acc[s][ng][0], e0.y + acc[s][ng][1]);
            *p1 = h2u(e1.x + acc[s][ng][2], e1.y + acc[s][ng][3]);
        }
    }
}

// ---------------------------------------------------------------------------
// MLP GEMM (fp32 accum): out = act(A @ Wt^T + bias). 128x128 tiles.
// ---------------------------------------------------------------------------
#define MTB 18432               // 128 rows * 144B

__global__ __launch_bounds__(256, 2)
void mlp_tc(const __half* __restrict__ A, const __half* __restrict__ Wt,
            const float* __restrict__ bias, void* __restrict__ outp, int act)
{
    extern __shared__ __align__(16) char smem[];
    const uint32_t sb = smem_u32(smem);

    const int tid = threadIdx.x, lane = tid & 31, warp = tid >> 5;
    const int wr = warp & 3, wc = warp >> 2;
    const int quad = lane >> 2, qt = lane & 3;
    const int n0 = blockIdx.x * 128, r0 = blockIdx.y * 128;

    int crow[4], ccol[4];
    #pragma unroll
    for (int i = 0; i < 4; ++i) {
        int c = tid + i * 256;
        crow[i] = c >> 3;
        ccol[i] = (c & 7) * 8;
    }

    auto issue = [&](int kc, int buf) {
        const uint32_t Ab = sb + buf * 2 * MTB;
        const uint32_t Wb = Ab + MTB;
        #pragma unroll
        for (int i = 0; i < 4; ++i) {
            uint32_t d = crow[i] * RSB + ccol[i] * 2;
            cpa16(Ab + d, A  + (size_t)(r0 + crow[i]) * 1024 + kc * 64 + ccol[i]);
            cpa16(Wb + d, Wt + (size_t)(n0 + crow[i]) * 1024 + kc * 64 + ccol[i]);
        }
    };

    const uint32_t laneA = (lane & 15) * RSB + (lane >> 4) * 16;
    const uint32_t laneK = ((lane & 7) + (lane >> 4) * 8) * RSB + ((lane >> 3) & 1) * 16;

    float acc[2][8][4] = {};

    issue(0, 0);
    CP_COMMIT();

    for (int kc = 0; kc < 16; ++kc) {
        const int buf = kc & 1;
        if (kc < 15) { issue(kc + 1, buf ^ 1); CP_COMMIT(); CP_WAIT(1); }
        else CP_WAIT(0);
        __syncthreads();

        const uint32_t Ab = sb + buf * 2 * MTB;
        const uint32_t Wb = Ab + MTB;

        #pragma unroll
        for (int kg = 0; kg < 4; ++kg) {
            uint32_t a[2][4];
            ldsm4(a[0], Ab + (wr * 32) * RSB + kg * 32 + laneA);
            ldsm4(a[1], Ab + (wr * 32 + 16) * RSB + kg * 32 + laneA);
            #pragma unroll
            for (int ngp = 0; ngp < 4; ++ngp) {
                uint32_t wf[4];
                ldsm4(wf, Wb + (wc * 64 + ngp * 16) * RSB + kg * 32 + laneK);
                mma16(acc[0][2 * ngp],     a[0], wf);
                mma16(acc[1][2 * ngp],     a[1], wf);
                mma16(acc[0][2 * ngp + 1], a[0], wf + 2);
                mma16(acc[1][2 * ngp + 1], a[1], wf + 2);
            }
        }
        __syncthreads();
    }

    #pragma unroll
    for (int t = 0; t < 2; ++t) {
        const int rr = r0 + (wr * 2 + t) * 16 + quad;
        #pragma unroll
        for (int ng = 0; ng < 8; ++ng) {
            const int col = n0 + (wc * 8 + ng) * 8 + 2 * qt;
            float2 bv = *(const float2*)(bias + col);
            float x0 = acc[t][ng][0] + bv.x, x1 = acc[t][ng][1] + bv.y;
            float x2 = acc[t][ng][2] + bv.x, x3 = acc[t][ng][3] + bv.y;
            if (act) {
                x0 = x0 / (1.f + __expf(-x0)); x1 = x1 / (1.f + __expf(-x1));
                x2 = x2 / (1.f + __expf(-x2)); x3 = x3 / (1.f + __expf(-x3));
                __half* o = (__half*)outp;
                *(uint32_t*)(o + (size_t)rr * 1024 + col)       = h2u(x0, x1);
                *(uint32_t*)(o + (size_t)(rr + 8) * 1024 + col) = h2u(x2, x3);
            } else {
                float* o = (float*)outp;
                *(float2*)(o + (size_t)rr * 1024 + col)       = make_float2(x0, x1);
                *(float2*)(o + (size_t)(rr + 8) * 1024 + col) = make_float2(x2, x3);
            }
        }
    }
}

// ---------------------------------------------------------------------------
extern "C" void kernel_launch(void* const* d_in, const int* in_sizes, int n_in,
                              void* d_out, int out_size)
{
    const float* q  = (const float*)d_in[0];
    const float* k  = (const float*)d_in[1];
    const float* v  = (const float*)d_in[2];
    const float* pe = (const float*)d_in[3];
    const float* w1 = (const float*)d_in[4];
    const float* b1 = (const float*)d_in[5];
    const float* w2 = (const float*)d_in[6];
    const float* b2 = (const float*)d_in[7];
    float* out = (float*)d_out;

    __half *qh, *kh, *vh, *xh, *hh, *w1h, *w2h;
    cudaGetSymbolAddress((void**)&qh,  g_qh);
    cudaGetSymbolAddress((void**)&kh,  g_kh);
    cudaGetSymbolAddress((void**)&vh,  g_vh);
    cudaGetSymbolAddress((void**)&xh,  g_xh);
    cudaGetSymbolAddress((void**)&hh,  g_hh);
    cudaGetSymbolAddress((void**)&w1h, g_w1h);
    cudaGetSymbolAddress((void**)&w2h, g_w2h);

    const int ATTN_SMEM = 5 * TB;                       // 46080
    const int PEV_SMEM  = 2 * EVA_TB + 2 * EVV_TB;      // 86016
    const int MLP_SMEM  = 4 * MTB;                      // 73728
    cudaFuncSetAttribute(attn_kernel, cudaFuncAttributeMaxDynamicSharedMemorySize, ATTN_SMEM);
    cudaFuncSetAttribute(pev_kernel,  cudaFuncAttributeMaxDynamicSharedMemorySize, PEV_SMEM);
    cudaFuncSetAttribute(mlp_tc,      cudaFuncAttributeMaxDynamicSharedMemorySize, MLP_SMEM);

    cvt3<<<dim3(4096, 3), 256>>>((const float4*)q, (const float4*)k, (const float4*)v,
                                 (uint2*)qh, (uint2*)kh, (uint2*)vh);
    transpose_h<<<dim3(32, 32), dim3(32, 8)>>>(w1, w1h);
    transpose_h<<<dim3(32, 32), dim3(32, 8)>>>(w2, w2h);

    attn_kernel<<<dim3(4, 16, 16), 128, ATTN_SMEM>>>(qh, kh, vh, xh);
    pev_kernel<<<dim3(16, 16), 256, PEV_SMEM>>>(pe, vh, xh);
    mlp_tc<<<dim3(8, 32), 256, MLP_SMEM>>>(xh, w1h, b1, hh, 1);
    mlp_tc<<<dim3(8, 32), 256, MLP_SMEM>>>(hh, w2h, b2, out, 0);
}

// round 8
// speedup vs baseline: 1.4735x; 1.4735x over previous
#include <cuda_runtime.h>
#include <cuda_fp16.h>
#include <cstdint>

// Scratch (allocation-free rule: device globals)
__device__ __align__(16) __half g_qh[4194304];
__device__ __align__(16) __half g_kh[4194304];
__device__ __align__(16) __half g_vh[4194304];
__device__ __align__(16) __half g_peh[16777216];
__device__ __align__(16) __half g_xh[4194304];   // attention out (half), [B*N, D]
__device__ __align__(16) __half g_hh[4194304];   // MLP hidden (half), [B*N, D]
__device__ __align__(16) __half g_w1h[1048576];  // W1^T [out][in] half
__device__ __align__(16) __half g_w2h[1048576];  // W2^T [out][in] half

__device__ __forceinline__ uint32_t h2u(float a, float b) {
    __half2 h = __floats2half2_rn(a, b);
    return *reinterpret_cast<uint32_t*>(&h);
}
__device__ __forceinline__ uint32_t smem_u32(const void* p) {
    uint32_t a;
    asm("{ .reg .u64 t; cvta.to.shared.u64 t, %1; cvt.u32.u64 %0, t; }" : "=r"(a) : "l"(p));
    return a;
}
__device__ __forceinline__ void cpa16(uint32_t dst, const void* src) {
    asm volatile("cp.async.cg.shared.global [%0], [%1], 16;" :: "r"(dst), "l"(src));
}
#define CP_COMMIT() asm volatile("cp.async.commit_group;" ::: "memory")
#define CP_WAIT(n)  asm volatile("cp.async.wait_group %0;" :: "n"(n) : "memory")

__device__ __forceinline__ void ldsm4(uint32_t* r, uint32_t a) {
    asm volatile("ldmatrix.sync.aligned.m8n8.x4.shared.b16 {%0,%1,%2,%3}, [%4];"
        : "=r"(r[0]), "=r"(r[1]), "=r"(r[2]), "=r"(r[3]) : "r"(a));
}
__device__ __forceinline__ void ldsm4t(uint32_t* r, uint32_t a) {
    asm volatile("ldmatrix.sync.aligned.m8n8.x4.trans.shared.b16 {%0,%1,%2,%3}, [%4];"
        : "=r"(r[0]), "=r"(r[1]), "=r"(r[2]), "=r"(r[3]) : "r"(a));
}

// fp32-accumulate MMA
__device__ __forceinline__ void mma16(float* c, const uint32_t* a, const uint32_t* b) {
    asm volatile("mma.sync.aligned.m16n8k16.row.col.f32.f16.f16.f32 "
        "{%0,%1,%2,%3}, {%4,%5,%6,%7}, {%8,%9}, {%0,%1,%2,%3};"
        : "+f"(c[0]), "+f"(c[1]), "+f"(c[2]), "+f"(c[3])
        : "r"(a[0]), "r"(a[1]), "r"(a[2]), "r"(a[3]), "r"(b[0]), "r"(b[1]));
}
// fp16-accumulate MMA (C/D = 2 regs of half2)
__device__ __forceinline__ void mma16h(uint32_t* c, const uint32_t* a, const uint32_t* b) {
    asm volatile("mma.sync.aligned.m16n8k16.row.col.f16.f16.f16.f16 "
        "{%0,%1}, {%2,%3,%4,%5}, {%6,%7}, {%0,%1};"
        : "+r"(c[0]), "+r"(c[1])
        : "r"(a[0]), "r"(a[1]), "r"(a[2]), "r"(a[3]), "r"(b[0]), "r"(b[1]));
}
__device__ __forceinline__ uint32_t ex2h2(uint32_t x) {
    uint32_t r; asm("ex2.approx.f16x2 %0, %1;" : "=r"(r) : "r"(x)); return r;
}
__device__ __forceinline__ uint32_t mulh2(uint32_t a, uint32_t b) {
    uint32_t r; asm("mul.rn.f16x2 %0, %1, %2;" : "=r"(r) : "r"(a), "r"(b)); return r;
}

// ---------------------------------------------------------------------------
// Prep kernels
// ---------------------------------------------------------------------------
__global__ void cvt3(const float4* __restrict__ q, const float4* __restrict__ k,
                     const float4* __restrict__ v, uint2* __restrict__ qo,
                     uint2* __restrict__ ko, uint2* __restrict__ vo)
{
    int i = blockIdx.x * blockDim.x + threadIdx.x;
    const float4* s = blockIdx.y == 0 ? q : (blockIdx.y == 1 ? k : v);
    uint2* d = blockIdx.y == 0 ? qo : (blockIdx.y == 1 ? ko : vo);
    float4 t = s[i];
    uint2 o; o.x = h2u(t.x, t.y); o.y = h2u(t.z, t.w);
    d[i] = o;
}

__global__ void cvt_f2h(const float4* __restrict__ src, uint2* __restrict__ dst, int n4)
{
    int i = blockIdx.x * blockDim.x + threadIdx.x;
    if (i < n4) {
        float4 v = src[i];
        uint2 o;
        o.x = h2u(v.x, v.y);
        o.y = h2u(v.z, v.w);
        dst[i] = o;
    }
}

__global__ void transpose_h(const float* __restrict__ src, __half* __restrict__ dst)
{
    __shared__ float t[32][33];
    int x = blockIdx.x * 32 + threadIdx.x;
    int y = blockIdx.y * 32 + threadIdx.y;
    #pragma unroll
    for (int j = 0; j < 32; j += 8)
        t[threadIdx.y + j][threadIdx.x] = src[(size_t)(y + j) * 1024 + x];
    __syncthreads();
    x = blockIdx.y * 32 + threadIdx.x;
    y = blockIdx.x * 32 + threadIdx.y;
    #pragma unroll
    for (int j = 0; j < 32; j += 8)
        dst[(size_t)(y + j) * 1024 + x] = __float2half_rn(t[threadIdx.x][threadIdx.y + j]);
}

// ---------------------------------------------------------------------------
// Fused attention: ctx = softmax(Q K^T * scale) @ V + pe @ V
// Softmax path (QK^T, P@V, P@1) in fp16-accumulate MMA with in-place
// HMUL2+EX2 softmax on S fragments; pe@V in fp32-accumulate (dominant term).
// V B-fragments shared between P@V and E@V. cp.async double-buffered tiles.
// ---------------------------------------------------------------------------
#define TB 9216                 // 64 rows * 144B
#define RSB 144

__global__ __launch_bounds__(128, 3)
void attn_kernel(const __half* __restrict__ qh, const __half* __restrict__ kh,
                 const __half* __restrict__ vh, const __half* __restrict__ peh,
                 __half* __restrict__ xout)
{
    extern __shared__ __align__(16) char smem[];
    const uint32_t sb = smem_u32(smem);

    const int b = blockIdx.x, h = blockIdx.y, q0 = blockIdx.z * 64;
    const int tid = threadIdx.x, lane = tid & 31, warp = tid >> 5;
    const int quad = lane >> 2, qt = lane & 3;
    const int rl0 = warp * 16 + quad, rh0 = rl0 + 8;

    const __half* qb  = qh  + ((size_t)(b * 16 + h) * 1024 + q0) * 64;
    const __half* kb  = kh  + (size_t)(b * 16 + h) * 65536;
    const __half* vb  = vh  + (size_t)(b * 16 + h) * 65536;
    const __half* peb = peh + ((size_t)h * 1024 + q0) * 1024;

    int crow[4], ccol[4];
    #pragma unroll
    for (int i = 0; i < 4; ++i) {
        int c = tid + i * 128;
        crow[i] = c >> 3;
        ccol[i] = (c & 7) * 8;
    }

    auto issue_tile = [&](int kt, int buf) {
        const int k0 = kt * 64;
        const uint32_t Kb = sb + TB * (1 + buf * 3);
        const uint32_t Vb = Kb + TB;
        const uint32_t Eb = Vb + TB;
        #pragma unroll
        for (int i = 0; i < 4; ++i) {
            uint32_t d = crow[i] * RSB + ccol[i] * 2;
            cpa16(Kb + d, kb + (size_t)(k0 + crow[i]) * 64 + ccol[i]);
            cpa16(Vb + d, vb + (size_t)(k0 + crow[i]) * 64 + ccol[i]);
            cpa16(Eb + d, peb + (size_t)crow[i] * 1024 + k0 + ccol[i]);
        }
    };

    // prologue: Q + tile 0
    #pragma unroll
    for (int i = 0; i < 4; ++i)
        cpa16(sb + crow[i] * RSB + ccol[i] * 2, qb + (size_t)crow[i] * 64 + ccol[i]);
    issue_tile(0, 0);
    CP_COMMIT();

    const uint32_t laneA = (lane & 15) * RSB + (lane >> 4) * 16;
    const uint32_t laneK = ((lane & 7) + (lane >> 4) * 8) * RSB + ((lane >> 3) & 1) * 16;
    const uint32_t laneV = ((lane & 7) + ((lane >> 3) & 1) * 8) * RSB + (lane >> 4) * 16;

    uint32_t qa[4][4];
    uint32_t os2[8][2] = {};       // P@V, fp16 accum
    uint32_t rsum[2] = {};         // P@1, fp16 accum
    float op[8][4] = {};           // pe@V, fp32 accum
    const float c2f = 0.125f * 1.44269504088896340736f;  // scale * log2(e)
    const uint32_t c2h = h2u(c2f, c2f);
    const uint32_t ones[2] = {0x3C003C00u, 0x3C003C00u};

    for (int kt = 0; kt < 16; ++kt) {
        const int buf = kt & 1;
        if (kt < 15) { issue_tile(kt + 1, buf ^ 1); CP_COMMIT(); CP_WAIT(1); }
        else CP_WAIT(0);
        __syncthreads();

        if (kt == 0) {
            #pragma unroll
            for (int kg = 0; kg < 4; ++kg)
                ldsm4(qa[kg], sb + warp * 16 * RSB + kg * 32 + laneA);
        }

        const uint32_t Kb = sb + TB * (1 + buf * 3);
        const uint32_t Vb = Kb + TB;
        const uint32_t Eb = Vb + TB;

        // ----- S = Q @ K^T (fp16 accum) -----
        uint32_t pd[8][2] = {};
        #pragma unroll
        for (int kg = 0; kg < 4; ++kg)
            #pragma unroll
            for (int ngp = 0; ngp < 4; ++ngp) {
                uint32_t kf[4];
                ldsm4(kf, Kb + ngp * (16 * RSB) + kg * 32 + laneK);
                mma16h(pd[2 * ngp], qa[kg], kf);
                mma16h(pd[2 * ngp + 1], qa[kg], kf + 2);
            }

        // ----- P = exp2(S * c2), in place -----
        #pragma unroll
        for (int ng = 0; ng < 8; ++ng) {
            pd[ng][0] = ex2h2(mulh2(pd[ng][0], c2h));
            pd[ng][1] = ex2h2(mulh2(pd[ng][1], c2h));
        }

        // ----- os += P @ V (fp16) ; op += E @ V (fp32) ; rsum += P @ 1 -----
        #pragma unroll
        for (int kg = 0; kg < 4; ++kg) {
            uint32_t pa[4] = {pd[2 * kg][0], pd[2 * kg][1],
                              pd[2 * kg + 1][0], pd[2 * kg + 1][1]};
            uint32_t ea[4];
            ldsm4(ea, Eb + warp * (16 * RSB) + kg * 32 + laneA);
            mma16h(rsum, pa, ones);
            #pragma unroll
            for (int ngp = 0; ngp < 4; ++ngp) {
                uint32_t vf[4];
                ldsm4t(vf, Vb + kg * (16 * RSB) + ngp * 32 + laneV);
                mma16h(os2[2 * ngp],     pa, vf);
                mma16 (op [2 * ngp],     ea, vf);
                mma16h(os2[2 * ngp + 1], pa, vf + 2);
                mma16 (op [2 * ngp + 1], ea, vf + 2);
            }
        }
        __syncthreads();
    }

    // Epilogue: ctx = os / rowsum + op -> half, layout [b, n, h*64 + c]
    const float il = 1.f / __low2float(*reinterpret_cast<__half2*>(&rsum[0]));
    const float ih = 1.f / __low2float(*reinterpret_cast<__half2*>(&rsum[1]));
    #pragma unroll
    for (int ng = 0; ng < 8; ++ng) {
        const int col = h * 64 + ng * 8 + qt * 2;
        float2 lo = __half22float2(*reinterpret_cast<__half2*>(&os2[ng][0]));
        float2 hi = __half22float2(*reinterpret_cast<__half2*>(&os2[ng][1]));
        *(uint32_t*)(xout + ((size_t)b * 1024 + q0 + rl0) * 1024 + col) =
            h2u(lo.x * il + op[ng][0], lo.y * il + op[ng][1]);
        *(uint32_t*)(xout + ((size_t)b * 1024 + q0 + rh0) * 1024 + col) =
            h2u(hi.x * ih + op[ng][2], hi.y * ih + op[ng][3]);
    }
}

// ---------------------------------------------------------------------------
// MLP GEMM (fp32 accum): out = act(A @ Wt^T + bias). 128x128 tiles.
// ---------------------------------------------------------------------------
#define MTB 18432               // 128 rows * 144B

__global__ __launch_bounds__(256, 2)
void mlp_tc(const __half* __restrict__ A, const __half* __restrict__ Wt,
            const float* __restrict__ bias, void* __restrict__ outp, int act)
{
    extern __shared__ __align__(16) char smem[];
    const uint32_t sb = smem_u32(smem);

    const int tid = threadIdx.x, lane = tid & 31, warp = tid >> 5;
    const int wr = warp & 3, wc = warp >> 2;
    const int quad = lane >> 2, qt = lane & 3;
    const int n0 = blockIdx.x * 128, r0 = blockIdx.y * 128;

    int crow[4], ccol[4];
    #pragma unroll
    for (int i = 0; i < 4; ++i) {
        int c = tid + i * 256;
        crow[i] = c >> 3;
        ccol[i] = (c & 7) * 8;
    }

    auto issue = [&](int kc, int buf) {
        const uint32_t Ab = sb + buf * 2 * MTB;
        const uint32_t Wb = Ab + MTB;
        #pragma unroll
        for (int i = 0; i < 4; ++i) {
            uint32_t d = crow[i] * RSB + ccol[i] * 2;
            cpa16(Ab + d, A  + (size_t)(r0 + crow[i]) * 1024 + kc * 64 + ccol[i]);
            cpa16(Wb + d, Wt + (size_t)(n0 + crow[i]) * 1024 + kc * 64 + ccol[i]);
        }
    };

    const uint32_t laneA = (lane & 15) * RSB + (lane >> 4) * 16;
    const uint32_t laneK = ((lane & 7) + (lane >> 4) * 8) * RSB + ((lane >> 3) & 1) * 16;

    float acc[2][8][4] = {};

    issue(0, 0);
    CP_COMMIT();

    for (int kc = 0; kc < 16; ++kc) {
        const int buf = kc & 1;
        if (kc < 15) { issue(kc + 1, buf ^ 1); CP_COMMIT(); CP_WAIT(1); }
        else CP_WAIT(0);
        __syncthreads();

        const uint32_t Ab = sb + buf * 2 * MTB;
        const uint32_t Wb = Ab + MTB;

        #pragma unroll
        for (int kg = 0; kg < 4; ++kg) {
            uint32_t a[2][4];
            ldsm4(a[0], Ab + (wr * 32) * RSB + kg * 32 + laneA);
            ldsm4(a[1], Ab + (wr * 32 + 16) * RSB + kg * 32 + laneA);
            #pragma unroll
            for (int ngp = 0; ngp < 4; ++ngp) {
                uint32_t wf[4];
                ldsm4(wf, Wb + (wc * 64 + ngp * 16) * RSB + kg * 32 + laneK);
                mma16(acc[0][2 * ngp],     a[0], wf);
                mma16(acc[1][2 * ngp],     a[1], wf);
                mma16(acc[0][2 * ngp + 1], a[0], wf + 2);
                mma16(acc[1][2 * ngp + 1], a[1], wf + 2);
            }
        }
        __syncthreads();
    }

    #pragma unroll
    for (int t = 0; t < 2; ++t) {
        const int rr = r0 + (wr * 2 + t) * 16 + quad;
        #pragma unroll
        for (int ng = 0; ng < 8; ++ng) {
            const int col = n0 + (wc * 8 + ng) * 8 + 2 * qt;
            float2 bv = *(const float2*)(bias + col);
            float x0 = acc[t][ng][0] + bv.x, x1 = acc[t][ng][1] + bv.y;
            float x2 = acc[t][ng][2] + bv.x, x3 = acc[t][ng][3] + bv.y;
            if (act) {
                x0 = x0 / (1.f + __expf(-x0)); x1 = x1 / (1.f + __expf(-x1));
                x2 = x2 / (1.f + __expf(-x2)); x3 = x3 / (1.f + __expf(-x3));
                __half* o = (__half*)outp;
                *(uint32_t*)(o + (size_t)rr * 1024 + col)       = h2u(x0, x1);
                *(uint32_t*)(o + (size_t)(rr + 8) * 1024 + col) = h2u(x2, x3);
            } else {
                float* o = (float*)outp;
                *(float2*)(o + (size_t)rr * 1024 + col)       = make_float2(x0, x1);
                *(float2*)(o + (size_t)(rr + 8) * 1024 + col) = make_float2(x2, x3);
            }
        }
    }
}

// ---------------------------------------------------------------------------
extern "C" void kernel_launch(void* const* d_in, const int* in_sizes, int n_in,
                              void* d_out, int out_size)
{
    const float* q  = (const float*)d_in[0];
    const float* k  = (const float*)d_in[1];
    const float* v  = (const float*)d_in[2];
    const float* pe = (const float*)d_in[3];
    const float* w1 = (const float*)d_in[4];
    const float* b1 = (const float*)d_in[5];
    const float* w2 = (const float*)d_in[6];
    const float* b2 = (const float*)d_in[7];
    float* out = (float*)d_out;

    __half *qh, *kh, *vh, *peh, *xh, *hh, *w1h, *w2h;
    cudaGetSymbolAddress((void**)&qh,  g_qh);
    cudaGetSymbolAddress((void**)&kh,  g_kh);
    cudaGetSymbolAddress((void**)&vh,  g_vh);
    cudaGetSymbolAddress((void**)&peh, g_peh);
    cudaGetSymbolAddress((void**)&xh,  g_xh);
    cudaGetSymbolAddress((void**)&hh,  g_hh);
    cudaGetSymbolAddress((void**)&w1h, g_w1h);
    cudaGetSymbolAddress((void**)&w2h, g_w2h);

    const int ATTN_SMEM = 7 * TB;        // Q + 2x(K,V,E) = 64512 B
    const int MLP_SMEM  = 4 * MTB;       // 73728 B
    cudaFuncSetAttribute(attn_kernel, cudaFuncAttributeMaxDynamicSharedMemorySize, ATTN_SMEM);
    cudaFuncSetAttribute(mlp_tc,      cudaFuncAttributeMaxDynamicSharedMemorySize, MLP_SMEM);

    cvt3<<<dim3(4096, 3), 256>>>((const float4*)q, (const float4*)k, (const float4*)v,
                                 (uint2*)qh, (uint2*)kh, (uint2*)vh);
    cvt_f2h<<<16384, 256>>>((const float4*)pe, (uint2*)peh, 4194304);
    transpose_h<<<dim3(32, 32), dim3(32, 8)>>>(w1, w1h);
    transpose_h<<<dim3(32, 32), dim3(32, 8)>>>(w2, w2h);

    attn_kernel<<<dim3(4, 16, 16), 128, ATTN_SMEM>>>(qh, kh, vh, peh, xh);
    mlp_tc<<<dim3(8, 32), 256, MLP_SMEM>>>(xh, w1h, b1, hh, 1);
    mlp_tc<<<dim3(8, 32), 256, MLP_SMEM>>>(hh, w2h, b2, out, 0);
}